// round 1
// baseline (speedup 1.0000x reference)
#include <cuda_runtime.h>
#include <cuda_bf16.h>
#include <math.h>

#define KG   256
#define DG   12
#define CG   9
#define HG   32
#define NIN  15          // DG + 3
#define NEPS 1e-8f

__global__ __launch_bounds__(256) void gpc_kernel(
    const float* __restrict__ probe,   // [N,3]
    const float* __restrict__ mu,      // [K,3]
    const float* __restrict__ log_s,   // [K,3]
    const float* __restrict__ q,       // [K,4]
    const float* __restrict__ F,       // [K,D]
    const float* __restrict__ W1,      // [NIN,H]
    const float* __restrict__ b1,      // [H]
    const float* __restrict__ W2,      // [H,C]
    const float* __restrict__ b2,      // [C]
    float* __restrict__ out_sh,        // [N,C]
    float* __restrict__ out_latent,    // [N,D]
    float* __restrict__ out_w,         // [N,K]
    int N)
{
    // per-gaussian packed params: p00 p01 p02 p11 p12 p22 mux muy muz rad2 pad pad
    __shared__ float s_g[KG * 12];
    __shared__ float s_F[KG * DG];
    __shared__ float s_W1[NIN * HG];
    __shared__ float s_b1[HG];
    __shared__ float s_W2[HG * CG];
    __shared__ float s_b2[CG];

    const int t = threadIdx.x;

    // ---- per-gaussian precompute: one thread per gaussian (blockDim == KG) ----
    {
        const int k = t;
        float qw = q[k*4+0], qx = q[k*4+1], qy = q[k*4+2], qz = q[k*4+3];
        float inv = 1.0f / (sqrtf(qw*qw + qx*qx + qy*qy + qz*qz) + NEPS);
        qw *= inv; qx *= inv; qy *= inv; qz *= inv;

        float r00 = 1.f - 2.f*(qy*qy + qz*qz);
        float r01 = 2.f*(qx*qy - qw*qz);
        float r02 = 2.f*(qx*qz + qw*qy);
        float r10 = 2.f*(qx*qy + qw*qz);
        float r11 = 1.f - 2.f*(qx*qx + qz*qz);
        float r12 = 2.f*(qy*qz - qw*qx);
        float r20 = 2.f*(qx*qz - qw*qy);
        float r21 = 2.f*(qy*qz + qw*qx);
        float r22 = 1.f - 2.f*(qx*qx + qy*qy);

        float sx = expf(log_s[k*3+0]);
        float sy = expf(log_s[k*3+1]);
        float sz = expf(log_s[k*3+2]);
        float ix = 1.f / (sx*sx + NEPS);
        float iy = 1.f / (sy*sy + NEPS);
        float iz = 1.f / (sz*sz + NEPS);

        // precision[i][l] = sum_j R[i][j] * iv[j] * R[l][j]   (symmetric)
        float p00 = r00*r00*ix + r01*r01*iy + r02*r02*iz;
        float p01 = r00*r10*ix + r01*r11*iy + r02*r12*iz;
        float p02 = r00*r20*ix + r01*r21*iy + r02*r22*iz;
        float p11 = r10*r10*ix + r11*r11*iy + r12*r12*iz;
        float p12 = r10*r20*ix + r11*r21*iy + r12*r22*iz;
        float p22 = r20*r20*ix + r21*r21*iy + r22*r22*iz;

        float smax = fmaxf(sx, fmaxf(sy, sz));
        float rad = 3.f * smax;

        float* g = s_g + k*12;
        g[0] = p00; g[1] = p01; g[2] = p02;
        g[3] = p11; g[4] = p12; g[5] = p22;
        g[6] = mu[k*3+0]; g[7] = mu[k*3+1]; g[8] = mu[k*3+2];
        g[9] = rad * rad; g[10] = 0.f; g[11] = 0.f;
    }
    for (int i = t; i < KG*DG;  i += 256) s_F[i]  = F[i];
    for (int i = t; i < NIN*HG; i += 256) s_W1[i] = W1[i];
    for (int i = t; i < HG*CG;  i += 256) s_W2[i] = W2[i];
    if (t < HG) s_b1[t] = b1[t];
    if (t < CG) s_b2[t] = b2[t];
    __syncthreads();

    const int n = blockIdx.x * 256 + t;
    if (n >= N) return;

    const float px = probe[n*3+0];
    const float py = probe[n*3+1];
    const float pz = probe[n*3+2];

    float4* wv = reinterpret_cast<float4*>(out_w + (size_t)n * KG);

    // ---- pass 1: gvals (unnormalized) -> staged into weights output; sum in regs ----
    float sum = 0.f;
    for (int k0 = 0; k0 < KG; k0 += 4) {
        float gv[4];
        #pragma unroll
        for (int u = 0; u < 4; u++) {
            const float* g = s_g + (k0 + u) * 12;
            float dx = px - g[6], dy = py - g[7], dz = pz - g[8];
            float d2 = dx*dx + dy*dy + dz*dz;
            float m  = g[0]*dx*dx + g[3]*dy*dy + g[5]*dz*dz
                     + 2.f*(g[1]*dx*dy + g[2]*dx*dz + g[4]*dy*dz);
            float e  = __expf(-0.5f * m);
            gv[u] = (d2 < g[9]) ? e : 0.f;
            sum += gv[u];
        }
        float4 gq; gq.x = gv[0]; gq.y = gv[1]; gq.z = gv[2]; gq.w = gv[3];
        wv[k0 >> 2] = gq;
    }
    const float invs = 1.f / (sum + NEPS);

    // ---- pass 2: normalize weights in place (L2-hot), accumulate latent ----
    float lat[DG];
    #pragma unroll
    for (int d = 0; d < DG; d++) lat[d] = 0.f;

    for (int k0 = 0; k0 < KG; k0 += 4) {
        float4 gq = wv[k0 >> 2];
        gq.x *= invs; gq.y *= invs; gq.z *= invs; gq.w *= invs;
        wv[k0 >> 2] = gq;
        const float* f0 = s_F + k0 * DG;
        #pragma unroll
        for (int d = 0; d < DG; d++)
            lat[d] += gq.x * f0[d] + gq.y * f0[DG + d]
                    + gq.z * f0[2*DG + d] + gq.w * f0[3*DG + d];
    }

    #pragma unroll
    for (int d = 0; d < DG; d++) out_latent[(size_t)n * DG + d] = lat[d];

    // ---- MLP: [latent, pos] @ W1 + b1 -> relu -> @ W2 + b2 ----
    float in[NIN];
    #pragma unroll
    for (int d = 0; d < DG; d++) in[d] = lat[d];
    in[12] = px; in[13] = py; in[14] = pz;

    float sh[CG];
    #pragma unroll
    for (int c = 0; c < CG; c++) sh[c] = s_b2[c];

    #pragma unroll
    for (int j = 0; j < HG; j++) {
        float h = s_b1[j];
        #pragma unroll
        for (int i = 0; i < NIN; i++) h += in[i] * s_W1[i*HG + j];
        h = fmaxf(h, 0.f);
        #pragma unroll
        for (int c = 0; c < CG; c++) sh[c] += h * s_W2[j*CG + c];
    }
    #pragma unroll
    for (int c = 0; c < CG; c++) out_sh[(size_t)n * CG + c] = sh[c];
}

extern "C" void kernel_launch(void* const* d_in, const int* in_sizes, int n_in,
                              void* d_out, int out_size) {
    const float* probe = (const float*)d_in[0];
    const float* mu    = (const float*)d_in[1];
    const float* log_s = (const float*)d_in[2];
    const float* q     = (const float*)d_in[3];
    const float* F     = (const float*)d_in[4];
    const float* W1    = (const float*)d_in[5];
    const float* b1    = (const float*)d_in[6];
    const float* W2    = (const float*)d_in[7];
    const float* b2    = (const float*)d_in[8];

    const int N = in_sizes[0] / 3;

    float* out        = (float*)d_out;
    float* out_sh     = out;                            // [N, C]
    float* out_latent = out + (size_t)N * CG;           // [N, D]
    float* out_w      = out_latent + (size_t)N * DG;    // [N, K]

    const int blocks = (N + 255) / 256;
    gpc_kernel<<<blocks, 256>>>(probe, mu, log_s, q, F, W1, b1, W2, b2,
                                out_sh, out_latent, out_w, N);
}

// round 2
// speedup vs baseline: 1.1640x; 1.1640x over previous
#include <cuda_runtime.h>
#include <cuda_bf16.h>
#include <math.h>

#define KG   256
#define DG   12
#define CG   9
#define HG   32
#define NIN  15          // DG + 3
#define NEPS 1e-8f
#define LOG2E 1.4426950408889634f

struct alignas(16) G4 { float4 a; float4 b; float4 c; };
// a = (c00, c01, c02, c11)   coefficients pre-scaled: diag *= -0.5*log2e, offdiag *= -log2e
// b = (c12, c22, mux, muy)
// c = (muz, rad2, 0, 0)

__global__ __launch_bounds__(256, 3) void gpc_kernel(
    const float* __restrict__ probe,   // [N,3]
    const float* __restrict__ mu,      // [K,3]
    const float* __restrict__ log_s,   // [K,3]
    const float* __restrict__ q,       // [K,4]
    const float* __restrict__ F,       // [K,D]
    const float* __restrict__ W1,      // [NIN,H]
    const float* __restrict__ b1,      // [H]
    const float* __restrict__ W2,      // [H,C]
    const float* __restrict__ b2,      // [C]
    float* __restrict__ out_sh,        // [N,C]
    float* __restrict__ out_latent,    // [N,D]
    float* __restrict__ out_w,         // [N,K]
    int N)
{
    __shared__ G4   s_g[KG];
    __shared__ float s_F[KG * DG];
    __shared__ float s_W1t[HG * 16];   // transposed W1, padded: [j][i], i in 0..15
    __shared__ float s_W2p[HG * 12];   // padded W2: [j][c], c in 0..11
    __shared__ float s_b1[HG];
    __shared__ float s_b2[12];

    const int t = threadIdx.x;

    // ---- per-gaussian precompute: one thread per gaussian (blockDim == KG) ----
    {
        const int k = t;
        float qw = q[k*4+0], qx = q[k*4+1], qy = q[k*4+2], qz = q[k*4+3];
        float inv = 1.0f / (sqrtf(qw*qw + qx*qx + qy*qy + qz*qz) + NEPS);
        qw *= inv; qx *= inv; qy *= inv; qz *= inv;

        float r00 = 1.f - 2.f*(qy*qy + qz*qz);
        float r01 = 2.f*(qx*qy - qw*qz);
        float r02 = 2.f*(qx*qz + qw*qy);
        float r10 = 2.f*(qx*qy + qw*qz);
        float r11 = 1.f - 2.f*(qx*qx + qz*qz);
        float r12 = 2.f*(qy*qz - qw*qx);
        float r20 = 2.f*(qx*qz - qw*qy);
        float r21 = 2.f*(qy*qz + qw*qx);
        float r22 = 1.f - 2.f*(qx*qx + qy*qy);

        float sx = expf(log_s[k*3+0]);
        float sy = expf(log_s[k*3+1]);
        float sz = expf(log_s[k*3+2]);
        float ix = 1.f / (sx*sx + NEPS);
        float iy = 1.f / (sy*sy + NEPS);
        float iz = 1.f / (sz*sz + NEPS);

        float p00 = r00*r00*ix + r01*r01*iy + r02*r02*iz;
        float p01 = r00*r10*ix + r01*r11*iy + r02*r12*iz;
        float p02 = r00*r20*ix + r01*r21*iy + r02*r22*iz;
        float p11 = r10*r10*ix + r11*r11*iy + r12*r12*iz;
        float p12 = r10*r20*ix + r11*r21*iy + r12*r22*iz;
        float p22 = r20*r20*ix + r21*r21*iy + r22*r22*iz;

        float smax = fmaxf(sx, fmaxf(sy, sz));
        float rad = 3.f * smax;

        const float dgs = -0.5f * LOG2E;   // diag scale
        const float ogs = -LOG2E;          // off-diag scale (folds the 2x)
        G4 g;
        g.a = make_float4(p00*dgs, p01*ogs, p02*ogs, p11*dgs);
        g.b = make_float4(p12*ogs, p22*dgs, mu[k*3+0], mu[k*3+1]);
        g.c = make_float4(mu[k*3+2], rad*rad, 0.f, 0.f);
        s_g[k] = g;
    }
    for (int i = t; i < KG*DG; i += 256) s_F[i] = F[i];
    // W1 transpose+pad: W1 is [NIN][HG] row-major -> s_W1t[j*16 + i]
    for (int idx = t; idx < NIN*HG; idx += 256) {
        int i = idx / HG, j = idx % HG;
        s_W1t[j*16 + i] = W1[idx];
    }
    // W2 pad: W2 is [HG][CG] -> s_W2p[j*12 + c]
    for (int idx = t; idx < HG*CG; idx += 256) {
        int j = idx / CG, c = idx % CG;
        s_W2p[j*12 + c] = W2[idx];
    }
    if (t < HG) { s_W1t[t*16 + 15] = 0.f; s_b1[t] = b1[t]; }
    if (t < HG*3) { int j = t / 3, c = 9 + t % 3; s_W2p[j*12 + c] = 0.f; }
    if (t < 12) s_b2[t] = (t < CG) ? b2[t] : 0.f;
    __syncthreads();

    const int n = blockIdx.x * 256 + t;
    if (n >= N) return;

    const float px = probe[n*3+0];
    const float py = probe[n*3+1];
    const float pz = probe[n*3+2];

    float4* wv = reinterpret_cast<float4*>(out_w + (size_t)n * KG);

    // ---- pass 1: unnormalized gvals -> staged into out_w; sum in regs ----
    float sum = 0.f;
    #pragma unroll 4
    for (int k0 = 0; k0 < KG; k0 += 4) {
        float gv[4];
        #pragma unroll
        for (int u = 0; u < 4; u++) {
            const G4 g = s_g[k0 + u];
            float dx = px - g.b.z, dy = py - g.b.w, dz = pz - g.c.x;
            float d2 = dx*dx + dy*dy + dz*dz;
            // arg = -0.5*log2e*mahal (scales folded into coefficients)
            float arg = g.a.x*dx*dx + g.a.w*dy*dy + g.b.y*dz*dz
                      + g.a.y*dx*dy + g.a.z*dx*dz + g.b.x*dy*dz;
            float e = exp2f(arg);
            gv[u] = (d2 < g.c.y) ? e : 0.f;
            sum += gv[u];
        }
        wv[k0 >> 2] = make_float4(gv[0], gv[1], gv[2], gv[3]);
    }
    const float invs = 1.f / (sum + NEPS);

    // ---- pass 2: normalize weights in place (L2-hot), accumulate latent ----
    float lat[DG];
    #pragma unroll
    for (int d = 0; d < DG; d++) lat[d] = 0.f;

    const float4* sF4 = reinterpret_cast<const float4*>(s_F);
    for (int k0 = 0; k0 < KG; k0 += 4) {
        float4 gq = wv[k0 >> 2];
        gq.x *= invs; gq.y *= invs; gq.z *= invs; gq.w *= invs;
        wv[k0 >> 2] = gq;
        // F rows k0..k0+3, each 12 floats = 3 float4
        const float4* f0 = sF4 + k0 * 3;
        #pragma unroll
        for (int r = 0; r < 3; r++) {
            float4 a0 = f0[r], a1 = f0[3 + r], a2 = f0[6 + r], a3 = f0[9 + r];
            lat[r*4+0] += gq.x*a0.x + gq.y*a1.x + gq.z*a2.x + gq.w*a3.x;
            lat[r*4+1] += gq.x*a0.y + gq.y*a1.y + gq.z*a2.y + gq.w*a3.y;
            lat[r*4+2] += gq.x*a0.z + gq.y*a1.z + gq.z*a2.z + gq.w*a3.z;
            lat[r*4+3] += gq.x*a0.w + gq.y*a1.w + gq.z*a2.w + gq.w*a3.w;
        }
    }

    {
        float4* lo = reinterpret_cast<float4*>(out_latent + (size_t)n * DG);
        lo[0] = make_float4(lat[0], lat[1], lat[2], lat[3]);
        lo[1] = make_float4(lat[4], lat[5], lat[6], lat[7]);
        lo[2] = make_float4(lat[8], lat[9], lat[10], lat[11]);
    }

    // ---- MLP: [latent, pos, pad] (16) @ W1t -> relu -> @ W2p ----
    float4 in0 = make_float4(lat[0], lat[1], lat[2],  lat[3]);
    float4 in1 = make_float4(lat[4], lat[5], lat[6],  lat[7]);
    float4 in2 = make_float4(lat[8], lat[9], lat[10], lat[11]);
    float4 in3 = make_float4(px, py, pz, 0.f);

    float sh[12];
    #pragma unroll
    for (int c = 0; c < 12; c++) sh[c] = s_b2[c];

    const float4* w1v = reinterpret_cast<const float4*>(s_W1t);
    const float4* w2v = reinterpret_cast<const float4*>(s_W2p);
    #pragma unroll
    for (int j = 0; j < HG; j++) {
        float4 w0 = w1v[j*4+0], w1 = w1v[j*4+1], w2 = w1v[j*4+2], w3 = w1v[j*4+3];
        float h = s_b1[j]
            + in0.x*w0.x + in0.y*w0.y + in0.z*w0.z + in0.w*w0.w
            + in1.x*w1.x + in1.y*w1.y + in1.z*w1.z + in1.w*w1.w
            + in2.x*w2.x + in2.y*w2.y + in2.z*w2.z + in2.w*w2.w
            + in3.x*w3.x + in3.y*w3.y + in3.z*w3.z;
        h = fmaxf(h, 0.f);
        float4 v0 = w2v[j*3+0], v1 = w2v[j*3+1], v2 = w2v[j*3+2];
        sh[0] += h*v0.x; sh[1] += h*v0.y; sh[2]  += h*v0.z; sh[3]  += h*v0.w;
        sh[4] += h*v1.x; sh[5] += h*v1.y; sh[6]  += h*v1.z; sh[7]  += h*v1.w;
        sh[8] += h*v2.x; sh[9] += h*v2.y; sh[10] += h*v2.z; sh[11] += h*v2.w;
    }
    #pragma unroll
    for (int c = 0; c < CG; c++) out_sh[(size_t)n * CG + c] = sh[c];
}

extern "C" void kernel_launch(void* const* d_in, const int* in_sizes, int n_in,
                              void* d_out, int out_size) {
    const float* probe = (const float*)d_in[0];
    const float* mu    = (const float*)d_in[1];
    const float* log_s = (const float*)d_in[2];
    const float* q     = (const float*)d_in[3];
    const float* F     = (const float*)d_in[4];
    const float* W1    = (const float*)d_in[5];
    const float* b1    = (const float*)d_in[6];
    const float* W2    = (const float*)d_in[7];
    const float* b2    = (const float*)d_in[8];

    const int N = in_sizes[0] / 3;

    float* out        = (float*)d_out;
    float* out_sh     = out;                            // [N, C]
    float* out_latent = out + (size_t)N * CG;           // [N, D]
    float* out_w      = out_latent + (size_t)N * DG;    // [N, K]

    const int blocks = (N + 255) / 256;
    gpc_kernel<<<blocks, 256>>>(probe, mu, log_s, q, F, W1, b1, W2, b2,
                                out_sh, out_latent, out_w, N);
}

// round 3
// speedup vs baseline: 1.9423x; 1.6686x over previous
#include <cuda_runtime.h>
#include <cuda_bf16.h>
#include <math.h>

#define KG   256
#define DG   12
#define CG   9
#define HG   32
#define NIN  15
#define NEPS 1e-8f
#define LOG2E 1.4426950408889634f

// dynamic smem layout (float offsets)
#define OFF_G   0              // 256*12  packed gaussian params
#define OFF_F   3072           // 256*12
#define OFF_W1  6144           // 32*16   W1 transposed+padded
#define OFF_W2  6656           // 32*12   W2 padded
#define OFF_B1  7040           // 32
#define OFF_B2  7072           // 16 (12 used)
#define OFF_ST  7088           // 256*36  staging tile
#define SMEM_FLOATS (OFF_ST + 256*36)

__global__ __launch_bounds__(256, 3) void gpc_kernel(
    const float* __restrict__ probe,
    const float* __restrict__ mu,
    const float* __restrict__ log_s,
    const float* __restrict__ q,
    const float* __restrict__ F,
    const float* __restrict__ W1,
    const float* __restrict__ b1,
    const float* __restrict__ W2,
    const float* __restrict__ b2,
    float* __restrict__ out_sh,        // [N,C]
    float* __restrict__ out_latent,    // [N,D]
    float* __restrict__ out_w,         // [N,K]
    int N)
{
    extern __shared__ float sm[];
    float* s_g   = sm + OFF_G;
    float* s_F   = sm + OFF_F;
    float* s_W1t = sm + OFF_W1;
    float* s_W2p = sm + OFF_W2;
    float* s_b1  = sm + OFF_B1;
    float* s_b2  = sm + OFF_B2;
    float* s_st  = sm + OFF_ST;

    const int t    = threadIdx.x;
    const int lane = t & 31;
    const int warp = t >> 5;

    // ---- per-gaussian precompute: thread t = gaussian t ----
    {
        const int k = t;
        float qw = q[k*4+0], qx = q[k*4+1], qy = q[k*4+2], qz = q[k*4+3];
        float inv = 1.0f / (sqrtf(qw*qw + qx*qx + qy*qy + qz*qz) + NEPS);
        qw *= inv; qx *= inv; qy *= inv; qz *= inv;

        float r00 = 1.f - 2.f*(qy*qy + qz*qz);
        float r01 = 2.f*(qx*qy - qw*qz);
        float r02 = 2.f*(qx*qz + qw*qy);
        float r10 = 2.f*(qx*qy + qw*qz);
        float r11 = 1.f - 2.f*(qx*qx + qz*qz);
        float r12 = 2.f*(qy*qz - qw*qx);
        float r20 = 2.f*(qx*qz - qw*qy);
        float r21 = 2.f*(qy*qz + qw*qx);
        float r22 = 1.f - 2.f*(qx*qx + qy*qy);

        float sx = expf(log_s[k*3+0]);
        float sy = expf(log_s[k*3+1]);
        float sz = expf(log_s[k*3+2]);
        float ix = 1.f / (sx*sx + NEPS);
        float iy = 1.f / (sy*sy + NEPS);
        float iz = 1.f / (sz*sz + NEPS);

        float p00 = r00*r00*ix + r01*r01*iy + r02*r02*iz;
        float p01 = r00*r10*ix + r01*r11*iy + r02*r12*iz;
        float p02 = r00*r20*ix + r01*r21*iy + r02*r22*iz;
        float p11 = r10*r10*ix + r11*r11*iy + r12*r12*iz;
        float p12 = r10*r20*ix + r11*r21*iy + r12*r22*iz;
        float p22 = r20*r20*ix + r21*r21*iy + r22*r22*iz;

        float smax = fmaxf(sx, fmaxf(sy, sz));
        float rad = 3.f * smax;

        const float sc = -0.5f * LOG2E;   // exp(-0.5 m) = exp2(sc * m)
        float4* g = reinterpret_cast<float4*>(s_g + k*12);
        g[0] = make_float4(p00*sc, 2.f*p01*sc, 2.f*p02*sc, p11*sc);
        g[1] = make_float4(2.f*p12*sc, p22*sc, mu[k*3+0], mu[k*3+1]);
        g[2] = make_float4(mu[k*3+2], rad*rad, 0.f, 0.f);
    }
    for (int i = t; i < KG*DG; i += 256) s_F[i] = F[i];
    for (int idx = t; idx < NIN*HG; idx += 256) {
        int i = idx / HG, j = idx % HG;
        s_W1t[j*16 + i] = W1[idx];
    }
    for (int idx = t; idx < HG*CG; idx += 256) {
        int j = idx / CG, c = idx % CG;
        s_W2p[j*12 + c] = W2[idx];
    }
    if (t < HG) { s_W1t[t*16 + 15] = 0.f; s_b1[t] = b1[t]; }
    if (t < HG*3) { int j = t / 3, c = 9 + t % 3; s_W2p[j*12 + c] = 0.f; }
    if (t < 16) s_b2[t] = (t < CG) ? b2[t] : 0.f;
    __syncthreads();

    const int nbase  = blockIdx.x * 256;       // block's first probe
    const int n      = nbase + t;              // this thread's probe
    const int nwbase = nbase + warp * 32;      // warp's first probe
    const bool valid = (n < N);

    float px = 0.f, py = 0.f, pz = 0.f;
    if (valid) { px = probe[n*3+0]; py = probe[n*3+1]; pz = probe[n*3+2]; }

    float* srow = s_st + t * 36;               // this thread's staging row

    float lat[DG];
    #pragma unroll
    for (int d = 0; d < DG; d++) lat[d] = 0.f;
    float sum = 0.f;

    const float4* g4 = reinterpret_cast<const float4*>(s_g);
    const float4* F4 = reinterpret_cast<const float4*>(s_F);

    // ---- pass 1: gvals (unnormalized) + latent; coalesced staging writes ----
    for (int c = 0; c < KG; c += 32) {
        #pragma unroll
        for (int q4 = 0; q4 < 8; q4++) {
            float gv[4];
            #pragma unroll
            for (int u = 0; u < 4; u++) {
                const int k = c + q4*4 + u;
                const float4 ga = g4[k*3+0];
                const float4 gb = g4[k*3+1];
                const float4 gc = g4[k*3+2];
                float dx = px - gb.z, dy = py - gb.w, dz = pz - gc.x;
                float d2 = fmaf(dx, dx, fmaf(dy, dy, dz*dz));
                float A  = fmaf(ga.x, dx, fmaf(ga.y, dy, ga.z*dz));
                float B  = fmaf(ga.w, dy, gb.x*dz);
                float Cc = gb.y * dz;
                float arg = fmaf(dx, A, fmaf(dy, B, dz*Cc));
                float e;
                asm("ex2.approx.f32 %0, %1;" : "=f"(e) : "f"(arg));
                float g = (d2 < gc.y) ? e : 0.f;
                gv[u] = g;
                sum += g;
                const float4 f0 = F4[k*3+0], f1 = F4[k*3+1], f2 = F4[k*3+2];
                lat[0] += g*f0.x; lat[1] += g*f0.y; lat[2]  += g*f0.z; lat[3]  += g*f0.w;
                lat[4] += g*f1.x; lat[5] += g*f1.y; lat[6]  += g*f1.z; lat[7]  += g*f1.w;
                lat[8] += g*f2.x; lat[9] += g*f2.y; lat[10] += g*f2.z; lat[11] += g*f2.w;
            }
            *reinterpret_cast<float4*>(srow + q4*4) = make_float4(gv[0], gv[1], gv[2], gv[3]);
        }
        __syncwarp();
        // warp writes its 32 probes' 32-float segments, fully coalesced
        #pragma unroll 4
        for (int p = 0; p < 32; p++) {
            int np = nwbase + p;
            if (np < N)
                out_w[(size_t)np * KG + c + lane] = s_st[(warp*32 + p)*36 + lane];
        }
        __syncwarp();
    }

    const float invs = 1.f / (sum + NEPS);
    #pragma unroll
    for (int d = 0; d < DG; d++) lat[d] *= invs;

    // ---- MLP: [latent, pos, pad](16) @ W1t -> relu -> @ W2p ----
    float4 in0 = make_float4(lat[0], lat[1], lat[2],  lat[3]);
    float4 in1 = make_float4(lat[4], lat[5], lat[6],  lat[7]);
    float4 in2 = make_float4(lat[8], lat[9], lat[10], lat[11]);

    float sh[12];
    #pragma unroll
    for (int c = 0; c < 12; c++) sh[c] = s_b2[c];

    const float4* w1v = reinterpret_cast<const float4*>(s_W1t);
    const float4* w2v = reinterpret_cast<const float4*>(s_W2p);
    #pragma unroll
    for (int j = 0; j < HG; j++) {
        float4 w0 = w1v[j*4+0], w1 = w1v[j*4+1], w2 = w1v[j*4+2], w3 = w1v[j*4+3];
        float h = s_b1[j]
            + in0.x*w0.x + in0.y*w0.y + in0.z*w0.z + in0.w*w0.w
            + in1.x*w1.x + in1.y*w1.y + in1.z*w1.z + in1.w*w1.w
            + in2.x*w2.x + in2.y*w2.y + in2.z*w2.z + in2.w*w2.w
            + px*w3.x + py*w3.y + pz*w3.z;
        h = fmaxf(h, 0.f);
        float4 v0 = w2v[j*3+0], v1 = w2v[j*3+1], v2 = w2v[j*3+2];
        sh[0] += h*v0.x; sh[1] += h*v0.y; sh[2]  += h*v0.z; sh[3]  += h*v0.w;
        sh[4] += h*v1.x; sh[5] += h*v1.y; sh[6]  += h*v1.z; sh[7]  += h*v1.w;
        sh[8] += h*v2.x; sh[9] += h*v2.y; sh[10] += h*v2.z; sh[11] += h*v2.w;
    }

    // ---- stage latent (12) + sh (9) -> coalesced output writes ----
    {
        float4* sr4 = reinterpret_cast<float4*>(srow);
        sr4[0] = make_float4(lat[0], lat[1], lat[2],  lat[3]);
        sr4[1] = make_float4(lat[4], lat[5], lat[6],  lat[7]);
        sr4[2] = make_float4(lat[8], lat[9], lat[10], lat[11]);
        srow[12] = sh[0]; srow[13] = sh[1]; srow[14] = sh[2];
        srow[15] = sh[3]; srow[16] = sh[4]; srow[17] = sh[5];
        srow[18] = sh[6]; srow[19] = sh[7]; srow[20] = sh[8];
    }
    __syncwarp();
    // latent: 32 probes * 12 = 384 contiguous floats
    #pragma unroll
    for (int i = 0; i < 12; i++) {
        int e = i*32 + lane;
        int p = e / 12, d = e % 12;
        if (nwbase + p < N)
            out_latent[(size_t)nwbase * DG + e] = s_st[(warp*32 + p)*36 + d];
    }
    // sh: 32 probes * 9 = 288 contiguous floats
    #pragma unroll
    for (int i = 0; i < 9; i++) {
        int e = i*32 + lane;
        int p = e / 9, d = e % 9;
        if (nwbase + p < N)
            out_sh[(size_t)nwbase * CG + e] = s_st[(warp*32 + p)*36 + 12 + d];
    }

    // ---- pass 2: coalesced in-place weight normalization ----
    #pragma unroll 2
    for (int p = 0; p < 32; p++) {
        float iv = __shfl_sync(0xffffffffu, invs, p);
        int np = nwbase + p;
        if (np < N) {
            float4* row = reinterpret_cast<float4*>(out_w + (size_t)np * KG);
            float4 a = row[lane];
            float4 b = row[lane + 32];
            a.x *= iv; a.y *= iv; a.z *= iv; a.w *= iv;
            b.x *= iv; b.y *= iv; b.z *= iv; b.w *= iv;
            row[lane] = a;
            row[lane + 32] = b;
        }
    }
}

extern "C" void kernel_launch(void* const* d_in, const int* in_sizes, int n_in,
                              void* d_out, int out_size) {
    const float* probe = (const float*)d_in[0];
    const float* mu    = (const float*)d_in[1];
    const float* log_s = (const float*)d_in[2];
    const float* q     = (const float*)d_in[3];
    const float* F     = (const float*)d_in[4];
    const float* W1    = (const float*)d_in[5];
    const float* b1    = (const float*)d_in[6];
    const float* W2    = (const float*)d_in[7];
    const float* b2    = (const float*)d_in[8];

    const int N = in_sizes[0] / 3;

    float* out        = (float*)d_out;
    float* out_sh     = out;                            // [N, C]
    float* out_latent = out + (size_t)N * CG;           // [N, D]
    float* out_w      = out_latent + (size_t)N * DG;    // [N, K]

    const size_t smem_bytes = SMEM_FLOATS * sizeof(float);
    cudaFuncSetAttribute(gpc_kernel, cudaFuncAttributeMaxDynamicSharedMemorySize,
                         (int)smem_bytes);

    const int blocks = (N + 255) / 256;
    gpc_kernel<<<blocks, 256, smem_bytes>>>(probe, mu, log_s, q, F, W1, b1, W2, b2,
                                            out_sh, out_latent, out_w, N);
}